// round 12
// baseline (speedup 1.0000x reference)
#include <cuda_runtime.h>
#include <cstddef>
#include <cstdint>

#define MM 1536
#define BLOCKS 8           /* one cluster */
#define WPB 6
#define STRIPS 48          /* BLOCKS * WPB */
#define TEND 1568          /* >= MM + 31, multiple of 8 */
#define TALLOC 1600
#define SBCOLS 1552        /* boundary columns (>= MM+1), 16B quads */

#define L2E  1.4426950408889634f
#define LN2  0.6931471805599453f
#define NEGB (-1.0e8f * L2E)

// Pre-skewed, padded theta: g_th3[((s*TALLOC + t)*3 + q)*128 + lane*4 + j]
__device__ float g_th3[(size_t)STRIPS * TALLOC * 384];

// ---- smem/DSMEM access helpers ----
__device__ __forceinline__ uint32_t mapa_cluster(uint32_t saddr, uint32_t rank) {
    uint32_t r;
    asm("mapa.shared::cluster.u32 %0, %1, %2;" : "=r"(r) : "r"(saddr), "r"(rank));
    return r;
}
__device__ __forceinline__ float4 ldv4_s(uint32_t a) {        // local smem, tear-free 128b
    float4 v;
    asm volatile("ld.volatile.shared.v4.f32 {%0,%1,%2,%3}, [%4];"
                 : "=f"(v.x), "=f"(v.y), "=f"(v.z), "=f"(v.w) : "r"(a) : "memory");
    return v;
}
__device__ __forceinline__ float4 ldv4_c(uint32_t a) {        // remote (DSMEM) 128b
    float4 v;
    asm volatile("ld.volatile.shared::cluster.v4.f32 {%0,%1,%2,%3}, [%4];"
                 : "=f"(v.x), "=f"(v.y), "=f"(v.z), "=f"(v.w) : "r"(a) : "memory");
    return v;
}
__device__ __forceinline__ void stv4_s(uint32_t a, float4 v) { // local smem store 128b
    asm volatile("st.volatile.shared.v4.f32 [%0], {%1,%2,%3,%4};"
                 :: "r"(a), "f"(v.x), "f"(v.y), "f"(v.z), "f"(v.w) : "memory");
}

__device__ __forceinline__ float ex2_(float x) {
    float y; asm("ex2.approx.ftz.f32 %0, %1;" : "=f"(y) : "f"(x)); return y;
}
__device__ __forceinline__ float lg2_(float x) {
    float y; asm("lg2.approx.ftz.f32 %0, %1;" : "=f"(y) : "f"(x)); return y;
}
__device__ __forceinline__ float lse3_(float a, float b, float c) {
    float hi = fmaxf(a, b), lo = fminf(a, b);
    float m  = fmaxf(hi, c), s2 = fminf(hi, c);
    return m + lg2_(1.0f + ex2_(lo - m) + ex2_(s2 - m));
}

// ---------------- transpose: theta -> padded skewed layout (unchanged) ------
#define TT 32
#define RG 8
#define NCOL (TT + RG - 1)
#define SROW (NCOL * 9)

__global__ void __launch_bounds__(256)
hmm_transpose_kernel(const float* __restrict__ theta)
{
    __shared__ float s[RG][SROW];
    const int g   = blockIdx.x;
    const int T0  = blockIdx.y * TT;
    const int r0  = blockIdx.z * RG;
    const int tid = threadIdx.x;
    const long NTOT = (long)MM * MM * 9;
    const int C0  = T0 - r0 - (RG - 1);

    #pragma unroll
    for (int row = 0; row < RG; row++) {
        long base = (long)(32 * g + r0 + row) * (MM * 9) + (long)C0 * 9;
        for (int i = tid; i < SROW; i += 256) {
            long idx = base + i;
            idx = idx < 0 ? 0 : (idx >= NTOT ? NTOT - 1 : idx);
            s[row][i] = theta[idx] * L2E;
        }
    }
    __syncthreads();

    float* outb = g_th3 + ((size_t)g * TALLOC + T0) * 384 + r0 * 4;
    #pragma unroll
    for (int k = 0; k < 12; k++) {
        int flat = tid + k * 256;
        int j    = flat & 3;
        int row  = (flat >> 2) & 7;
        int rest = flat >> 5;
        int q    = rest % 3;
        int t_i  = rest / 3;
        int e    = q * 4 + j;
        float v  = 0.0f;
        if (e < 9) v = s[row][(t_i - row + 7) * 9 + e];
        outb[(size_t)t_i * 384 + q * 128 + row * 4 + j] = v;
    }
}

// ---------------- wavefront DP: one cluster, 8 blocks x 6 warps -------------
__global__ void __launch_bounds__(192, 1) __cluster_dims__(BLOCKS, 1, 1)
hmm_fwd_kernel(float* __restrict__ out)
{
    extern __shared__ float4 smb[];   // [WPB][SBCOLS] boundary rows (row w = warp w's output)
    const int b   = blockIdx.x;
    const int wid = threadIdx.x >> 5;
    const int r   = threadIdx.x & 31;
    const int tid = threadIdx.x;

    // zero validity each launch (no global flag state at all)
    for (int i = tid; i < WPB * SBCOLS; i += 192)
        smb[i] = make_float4(0.f, 0.f, 0.f, 0.f);

    // cluster-wide barrier: zeroing visible everywhere before any DSMEM read
    asm volatile("barrier.cluster.arrive.aligned;" ::: "memory");
    asm volatile("barrier.cluster.wait.aligned;" ::: "memory");

    const int s = b * WPB + wid;
    const float4* tb4 = (const float4*)g_th3 + (size_t)s * TALLOC * 96 + r;

    const bool consS   = (wid > 0);                         // local smem consumer
    const bool consC   = (wid == 0 && b > 0);               // DSMEM consumer
    const bool lane0c  = (r == 0) && (consS || consC);
    const bool prod31  = (r == 31) && (s < STRIPS - 1);     // all producers write local smem

    uint32_t pS = (uint32_t)__cvta_generic_to_shared(smb + (size_t)wid * SBCOLS);
    uint32_t cS;   // consumer base address (shared::cta or shared::cluster)
    if (consC) {
        uint32_t local5 = (uint32_t)__cvta_generic_to_shared(smb + (size_t)(WPB - 1) * SBCOLS);
        cS = mapa_cluster(local5, (uint32_t)(b - 1));
    } else {
        cS = (uint32_t)__cvta_generic_to_shared(smb + (size_t)(consS ? (wid - 1) : 0) * SBCOLS);
    }

    float vM = NEGB, vX = NEGB, vY = NEGB;
    float duM, duX, duY;
    duM = duX = duY = (s == 0 && r == 0) ? 0.0f : NEGB;   // V(0,0) = 0

    float4 bq[8], spec[8];
    #pragma unroll
    for (int q = 0; q < 8; q++) {
        bq[q] = make_float4(NEGB, NEGB, NEGB, 1.0f);
        spec[q] = bq[q];
    }

    float4 thA[4][3], thB[4][3];
    auto loadGroup = [&](int tbase, float4 (&dst)[4][3]) {
        #pragma unroll
        for (int q = 0; q < 4; q++) {
            const float4* p = tb4 + (size_t)(tbase + q) * 96;
            dst[q][0] = __ldg(p);
            dst[q][1] = __ldg(p + 32);
            dst[q][2] = __ldg(p + 64);
        }
    };

    auto step = [&](int t, const float4 (&th)[3], float4 bb) {
        float nuM = __shfl_up_sync(0xffffffffu, vM, 1);
        float nuX = __shfl_up_sync(0xffffffffu, vX, 1);
        float nuY = __shfl_up_sync(0xffffffffu, vY, 1);
        if (r == 0) { nuM = bb.x; nuX = bb.y; nuY = bb.z; }
        int col = t - r;
        if ((unsigned)col < (unsigned)MM) {
            float a  = lse3_(duM + th[0].x, duX + th[0].y, duY + th[0].z); // M <- diag
            float b2 = lse3_(nuM + th[0].w, nuX + th[1].x, nuY + th[1].y); // X <- up
            float c  = lse3_(vM  + th[1].z, vX  + th[1].w, vY  + th[2].x); // Y <- left
            vM = a; vX = b2; vY = c;
            if (prod31) {
                int j = col + 1;
                stv4_s(pS + (uint32_t)j * 16, make_float4(a, b2, c, 1.0f));
            }
        }
        duM = nuM; duX = nuX; duY = nuY;
    };

    auto loadSpec = [&](int t0) {   // speculative prefetch of next chunk's boundary
        #pragma unroll
        for (int q = 0; q < 8; q++) {
            int c = t0 + 9 + q; if (c > MM) c = MM;
            uint32_t a = cS + (uint32_t)c * 16;
            spec[q] = consC ? ldv4_c(a) : ldv4_s(a);
        }
    };

    // ---- prologue ----
    loadGroup(0, thA);
    loadGroup(4, thB);
    if (lane0c) {
        bool ok;
        do {
            #pragma unroll
            for (int q = 0; q < 8; q++) {
                uint32_t a = cS + (uint32_t)(1 + q) * 16;
                bq[q] = consC ? ldv4_c(a) : ldv4_s(a);
            }
            ok = true;
            #pragma unroll
            for (int q = 0; q < 8; q++) ok = ok && (bq[q].w != 0.0f);
        } while (!ok);
    }

    // ---- main loop ----
    for (int t0 = 0; t0 < TEND; t0 += 8) {
        if (lane0c && t0 < MM) loadSpec(t0);   // issue early; validate at chunk end

        step(t0 + 0, thA[0], bq[0]);
        step(t0 + 1, thA[1], bq[1]);
        step(t0 + 2, thA[2], bq[2]);
        step(t0 + 3, thA[3], bq[3]);
        loadGroup(t0 + 8, thA);
        step(t0 + 4, thB[0], bq[4]);
        step(t0 + 5, thB[1], bq[5]);
        step(t0 + 6, thB[2], bq[6]);
        step(t0 + 7, thB[3], bq[7]);
        loadGroup(t0 + 12, thB);

        if (lane0c && t0 < MM) {               // validate + commit (retry rare)
            bool ok = true;
            #pragma unroll
            for (int q = 0; q < 8; q++) ok = ok && (spec[q].w != 0.0f);
            while (!ok) {
                loadSpec(t0);
                ok = true;
                #pragma unroll
                for (int q = 0; q < 8; q++) ok = ok && (spec[q].w != 0.0f);
            }
            #pragma unroll
            for (int q = 0; q < 8; q++) bq[q] = spec[q];
        }
    }

    if (s == STRIPS - 1 && r == 31) {
        out[0] = LN2 * lse3_(vM, vX, vY);
    }

    // keep smem alive until every block is done reading peers
    asm volatile("barrier.cluster.arrive.aligned;" ::: "memory");
    asm volatile("barrier.cluster.wait.aligned;" ::: "memory");
}

extern "C" void kernel_launch(void* const* d_in, const int* in_sizes, int n_in,
                              void* d_out, int out_size)
{
    const float* theta = (const float*)d_in[0];
    float* out = (float*)d_out;

    const size_t smemBytes = (size_t)WPB * SBCOLS * sizeof(float4);  // 148,992 B
    cudaFuncSetAttribute(hmm_fwd_kernel,
                         cudaFuncAttributeMaxDynamicSharedMemorySize,
                         (int)smemBytes);

    dim3 tgrid(STRIPS, TALLOC / TT, 32 / RG);
    hmm_transpose_kernel<<<tgrid, 256>>>(theta);
    hmm_fwd_kernel<<<BLOCKS, WPB * 32, smemBytes>>>(out);
}